// round 15
// baseline (speedup 1.0000x reference)
#include <cuda_runtime.h>
#include <cstdint>

#define SDIM 64
#define NOBJ 256
#define LSEQ 40
#define OD   128
#define KNB  17
#define NROWS (SDIM * NOBJ * KNB)   // 278528

typedef unsigned long long ull;

#define FMA2(d, a, b) asm("fma.rn.f32x2 %0, %1, %2, %0;" : "+l"(d) : "l"(a), "l"(b))
#define PACK2(d, lo, hi) asm("mov.b64 %0, {%1, %2};" : "=l"(d) : "f"(lo), "f"(hi))
#define UNPACK2(lo, hi, s) asm("mov.b64 {%0, %1}, %2;" : "=f"(lo), "=f"(hi) : "l"(s))

__device__ __forceinline__ uint32_t f2tf32(float f) {
    uint32_t u;
    asm("cvt.rna.tf32.f32 %0, %1;" : "=r"(u) : "f"(f));
    return u;
}

#define MMA_TF32(d, a, b) \
    asm("mma.sync.aligned.m16n8k8.row.col.f32.tf32.tf32.f32 " \
        "{%0,%1,%2,%3},{%4,%5,%6,%7},{%8,%9},{%0,%1,%2,%3};" \
        : "+f"((d)[0]), "+f"((d)[1]), "+f"((d)[2]), "+f"((d)[3]) \
        : "r"((a)[0]), "r"((a)[1]), "r"((a)[2]), "r"((a)[3]), \
          "r"((b)[0]), "r"((b)[1]))

// ---------------- device scratch ----------------
__device__ __align__(16) float g_f[SDIM * NOBJ * OD];
__device__ __align__(16) float g_lang[SDIM * LSEQ * OD];
__device__ __align__(16) float g_ri[NROWS * 10];
__device__ __align__(16) float g_fI[SDIM * NOBJ * OD];   // f * ins, per object
__device__ __align__(16) uint32_t g_w2t[128 * 128];       // rel_w2 as tf32 bits [k][n]
__device__ int   g_knn[NROWS];

// ---------------- kNN (blocks 0-63) + rel_w2 tf32 pre-convert (blocks 64-79) ----------------
__global__ __launch_bounds__(NOBJ) void knn_kernel(const float* __restrict__ coord,
                                                   const float* __restrict__ rel_w2) {
    int b = blockIdx.x;
    int tid = threadIdx.x;
    if (b >= SDIM) {
        int base = (b - SDIM) * 1024;
#pragma unroll
        for (int j = 0; j < 4; j++) {
            int e = base + tid + j * 256;
            g_w2t[e] = f2tf32(rel_w2[e]);
        }
        return;
    }
    __shared__ float cs[NOBJ * 3];
    int s = b;
    int n = tid;
    for (int i = n; i < NOBJ * 3; i += NOBJ) cs[i] = coord[s * NOBJ * 3 + i];
    __syncthreads();
    float cx = cs[n * 3 + 0], cy = cs[n * 3 + 1], cz = cs[n * 3 + 2];
    float best[KNB];
    int   bidx[KNB];
#pragma unroll
    for (int t = 0; t < KNB; t++) { best[t] = 3.4e38f; bidx[t] = 0; }
    for (int j = 0; j < NOBJ; j++) {
        float dx = cs[j * 3 + 0] - cx;
        float dy = cs[j * 3 + 1] - cy;
        float dz = cs[j * 3 + 2] - cz;
        float d2 = dx * dx + dy * dy + dz * dz;
        if (d2 < best[KNB - 1]) {
            int p = KNB - 1;
            while (p > 0 && best[p - 1] > d2) {
                best[p] = best[p - 1]; bidx[p] = bidx[p - 1]; p--;
            }
            best[p] = d2; bidx[p] = j;
        }
    }
#pragma unroll
    for (int t = 0; t < KNB; t++) {
        int row = (s * NOBJ + n) * KNB + t;
        int nb = bidx[t];
        g_knn[row] = nb;
        float cnx = cs[nb * 3 + 0], cny = cs[nb * 3 + 1], cnz = cs[nb * 3 + 2];
        float rx = cnx - cx, ry = cny - cy, rz = cnz - cz;
        float dist = sqrtf(rx * rx + ry * ry + rz * rz);
        float* ri = g_ri + row * 10;
        ri[0] = cnx; ri[1] = cny; ri[2] = cnz;
        ri[3] = cx;  ri[4] = cy;  ri[5] = cz;
        ri[6] = rx;  ri[7] = ry;  ri[8] = rz;
        ri[9] = dist;
    }
}

// ---------------- merged 2-layer MLPs, 64-row blocks ----------------
// blocks 0-255: feat rows b*64; blocks 256-295: lang rows (b-256)*64.
__global__ __launch_bounds__(256, 2) void mlp64_kernel(const float* __restrict__ feat,
                                                       const float* __restrict__ fw1,
                                                       const float* __restrict__ fb1,
                                                       const float* __restrict__ fw2,
                                                       const float* __restrict__ fb2,
                                                       const float* __restrict__ lang_feat,
                                                       const float* __restrict__ lw1,
                                                       const float* __restrict__ lb1,
                                                       const float* __restrict__ lw2,
                                                       const float* __restrict__ lb2) {
    extern __shared__ float smf[];
    uint32_t* hs = (uint32_t*)smf;      // 64r x 132c (tf32 of h)
    uint32_t* ws = hs + 64 * 132;       // 32k x 136n chunk
    uint32_t* xs = ws + 32 * 136;       // 64r x 36k chunk
    int tid = threadIdx.x, lane = tid & 31, warp = tid >> 5;
    int gid = lane >> 2, tig = lane & 3;
    int rbase = (warp & 1) * 32, cbase = (warp >> 1) * 32;

    const float *X, *W1, *B1, *W2, *B2;
    float* Y;
    int IN, row0;
    if (blockIdx.x < 256) {
        X = feat; W1 = fw1; B1 = fb1; W2 = fw2; B2 = fb2;
        Y = g_f; IN = 128; row0 = blockIdx.x * 64;
    } else {
        X = lang_feat; W1 = lw1; B1 = lb1; W2 = lw2; B2 = lb2;
        Y = g_lang; IN = 256; row0 = (blockIdx.x - 256) * 64;
    }

    float acc[2][4][4];
#pragma unroll
    for (int nt = 0; nt < 4; nt++) {
        int col = cbase + nt * 8 + 2 * tig;
        float v0 = B1[col], v1 = B1[col + 1];
#pragma unroll
        for (int mt = 0; mt < 2; mt++) {
            acc[mt][nt][0] = v0; acc[mt][nt][1] = v1;
            acc[mt][nt][2] = v0; acc[mt][nt][3] = v1;
        }
    }
    // ---- layer 1 ----
    for (int kc = 0; kc < IN; kc += 32) {
        __syncthreads();
        for (int i = tid; i < 32 * 128; i += 256) {
            int kk = i >> 7, n = i & 127;
            ws[kk * 136 + n] = f2tf32(W1[(size_t)(kc + kk) * 128 + n]);
        }
        for (int i = tid; i < 64 * 8; i += 256) {
            int r = i >> 3, k4 = i & 7;
            float4 v = *(const float4*)(X + (size_t)(row0 + r) * IN + kc + k4 * 4);
            xs[r * 36 + k4 * 4 + 0] = f2tf32(v.x);
            xs[r * 36 + k4 * 4 + 1] = f2tf32(v.y);
            xs[r * 36 + k4 * 4 + 2] = f2tf32(v.z);
            xs[r * 36 + k4 * 4 + 3] = f2tf32(v.w);
        }
        __syncthreads();
#pragma unroll
        for (int ks = 0; ks < 4; ks++) {
            int k0 = ks * 8;
            uint32_t a[2][4];
#pragma unroll
            for (int mt = 0; mt < 2; mt++) {
                int rb = rbase + mt * 16;
                a[mt][0] = xs[(rb + gid) * 36 + k0 + tig];
                a[mt][1] = xs[(rb + gid + 8) * 36 + k0 + tig];
                a[mt][2] = xs[(rb + gid) * 36 + k0 + tig + 4];
                a[mt][3] = xs[(rb + gid + 8) * 36 + k0 + tig + 4];
            }
#pragma unroll
            for (int nt = 0; nt < 4; nt++) {
                uint32_t bb[2];
                int n = cbase + nt * 8 + gid;
                bb[0] = ws[(k0 + tig) * 136 + n];
                bb[1] = ws[(k0 + tig + 4) * 136 + n];
                MMA_TF32(acc[0][nt], a[0], bb);
                MMA_TF32(acc[1][nt], a[1], bb);
            }
        }
    }
    // store h = relu(acc) as tf32 into hs[r][c]
#pragma unroll
    for (int mt = 0; mt < 2; mt++) {
        int r1 = rbase + mt * 16 + gid;
#pragma unroll
        for (int nt = 0; nt < 4; nt++) {
            int col = cbase + nt * 8 + 2 * tig;
            hs[r1 * 132 + col]           = f2tf32(fmaxf(acc[mt][nt][0], 0.f));
            hs[r1 * 132 + col + 1]       = f2tf32(fmaxf(acc[mt][nt][1], 0.f));
            hs[(r1 + 8) * 132 + col]     = f2tf32(fmaxf(acc[mt][nt][2], 0.f));
            hs[(r1 + 8) * 132 + col + 1] = f2tf32(fmaxf(acc[mt][nt][3], 0.f));
        }
    }
    // ---- layer 2 ----
#pragma unroll
    for (int nt = 0; nt < 4; nt++) {
        int col = cbase + nt * 8 + 2 * tig;
        float v0 = B2[col], v1 = B2[col + 1];
#pragma unroll
        for (int mt = 0; mt < 2; mt++) {
            acc[mt][nt][0] = v0; acc[mt][nt][1] = v1;
            acc[mt][nt][2] = v0; acc[mt][nt][3] = v1;
        }
    }
    for (int kc = 0; kc < 128; kc += 32) {
        __syncthreads();
        for (int i = tid; i < 32 * 128; i += 256) {
            int kk = i >> 7, n = i & 127;
            ws[kk * 136 + n] = f2tf32(W2[(size_t)(kc + kk) * 128 + n]);
        }
        __syncthreads();
#pragma unroll
        for (int ks = 0; ks < 4; ks++) {
            int k0 = ks * 8, kg = kc + k0;
            uint32_t a[2][4];
#pragma unroll
            for (int mt = 0; mt < 2; mt++) {
                int rb = rbase + mt * 16;
                a[mt][0] = hs[(rb + gid) * 132 + kg + tig];
                a[mt][1] = hs[(rb + gid + 8) * 132 + kg + tig];
                a[mt][2] = hs[(rb + gid) * 132 + kg + tig + 4];
                a[mt][3] = hs[(rb + gid + 8) * 132 + kg + tig + 4];
            }
#pragma unroll
            for (int nt = 0; nt < 4; nt++) {
                uint32_t bb[2];
                int n = cbase + nt * 8 + gid;
                bb[0] = ws[(k0 + tig) * 136 + n];
                bb[1] = ws[(k0 + tig + 4) * 136 + n];
                MMA_TF32(acc[0][nt], a[0], bb);
                MMA_TF32(acc[1][nt], a[1], bb);
            }
        }
    }
#pragma unroll
    for (int mt = 0; mt < 2; mt++) {
        int r1 = row0 + rbase + mt * 16 + gid;
#pragma unroll
        for (int nt = 0; nt < 4; nt++) {
            int col = cbase + nt * 8 + 2 * tig;
            *(float2*)(Y + (size_t)r1 * 128 + col)       = make_float2(acc[mt][nt][0], acc[mt][nt][1]);
            *(float2*)(Y + (size_t)(r1 + 8) * 128 + col) = make_float2(acc[mt][nt][2], acc[mt][nt][3]);
        }
    }
}

// ================= attins: logits + softmax + fI = f*(W@lang) + out init, per half-sentence =================
// grid 128, block 256.
__global__ __launch_bounds__(256) void attins_kernel(const float* __restrict__ lang_mask,
                                                     float* __restrict__ out) {
    extern __shared__ float sm[];
    float* fT     = sm;                   // 128k x 132n
    float* lT     = fT + 128 * 132;       // 128k x 44l
    float* WT     = lT + 128 * 44;        // 40l x 132m
    float* langS  = WT + 40 * 132;        // 40l x 128j
    float* mask_s = langS + 40 * 128;     // 40
    int s = blockIdx.x >> 1, nh = blockIdx.x & 1;
    int nbase = nh * 128;
    int tid = threadIdx.x;

    for (int i = tid; i < 128 * 32; i += 256) {
        int n = i & 127, k4 = i >> 7;
        const float* fp = g_f + (size_t)((s << 8) + nbase + n) * 128;
        float4 v = *(const float4*)(fp + k4 * 4);
        fT[(k4 * 4 + 0) * 132 + n] = v.x;
        fT[(k4 * 4 + 1) * 132 + n] = v.y;
        fT[(k4 * 4 + 2) * 132 + n] = v.z;
        fT[(k4 * 4 + 3) * 132 + n] = v.w;
        ((float4*)(out + (size_t)((s << 8) + nbase + n) * 128))[k4] = v;
    }
    for (int i = tid; i < 40 * 32; i += 256) {
        int l = i % 40, k4 = i / 40;
        float4 v = *(const float4*)(g_lang + (size_t)(s * 40 + l) * 128 + k4 * 4);
        lT[(k4 * 4 + 0) * 44 + l] = v.x;
        lT[(k4 * 4 + 1) * 44 + l] = v.y;
        lT[(k4 * 4 + 2) * 44 + l] = v.z;
        lT[(k4 * 4 + 3) * 44 + l] = v.w;
        ((float4*)(langS + l * 128))[k4] = v;
    }
    if (tid < 40) mask_s[tid] = lang_mask[s * 40 + tid];
    __syncthreads();

    // logits: WT[l][m] = <f_m, lang_l>
    {
        int tn = tid & 31, tl = tid >> 5;
        int n0 = tn * 4, l0 = tl * 5;
        ull acc[2][5];
#pragma unroll
        for (int np = 0; np < 2; np++)
#pragma unroll
            for (int u = 0; u < 5; u++) acc[np][u] = 0ull;
#pragma unroll 2
        for (int k = 0; k < 128; k++) {
            float4 fa = *(const float4*)(fT + k * 132 + n0);
            ull f01, f23;
            PACK2(f01, fa.x, fa.y); PACK2(f23, fa.z, fa.w);
#pragma unroll
            for (int u = 0; u < 5; u++) {
                float lg = lT[k * 44 + l0 + u];
                ull ld; PACK2(ld, lg, lg);
                FMA2(acc[0][u], f01, ld);
                FMA2(acc[1][u], f23, ld);
            }
        }
#pragma unroll
        for (int np = 0; np < 2; np++)
#pragma unroll
            for (int u = 0; u < 5; u++) {
                float a0, a1; UNPACK2(a0, a1, acc[np][u]);
                WT[(l0 + u) * 132 + n0 + 2 * np]     = a0;
                WT[(l0 + u) * 132 + n0 + 2 * np + 1] = a1;
            }
    }
    __syncthreads();

    // masked softmax + renorm per object m
    if (tid < 128) {
        int m = tid;
        float mx = -1e30f;
        for (int l = 0; l < 40; l++) mx = fmaxf(mx, WT[l * 132 + m]);
        float Z = 0.f, Zm = 0.f;
        for (int l = 0; l < 40; l++) {
            float e = __expf(WT[l * 132 + m] - mx);
            Z += e;
            float ew = e * mask_s[l];
            Zm += ew;
            WT[l * 132 + m] = ew;
        }
        float inv = 1.f / (Zm + 1e-7f * Z);
        for (int l = 0; l < 40; l++) WT[l * 132 + m] *= inv;
    }
    __syncthreads();

    // I = W @ lang ; write g_fI = f * I : 8m x 8j per thread
    {
        int tx = tid & 15, ty = tid >> 4;   // ty 0..15
        int j0 = tx * 8, m0 = ty * 8;
        ull acc[8][4];
#pragma unroll
        for (int m = 0; m < 8; m++)
#pragma unroll
            for (int jp = 0; jp < 4; jp++) acc[m][jp] = 0ull;
#pragma unroll 2
        for (int l = 0; l < 40; l++) {
            ulonglong2 la = *(const ulonglong2*)(langS + l * 128 + j0);
            ulonglong2 lb = *(const ulonglong2*)(langS + l * 128 + j0 + 4);
            float4 wa = *(const float4*)(WT + l * 132 + m0);
            float4 wb = *(const float4*)(WT + l * 132 + m0 + 4);
            float wr[8] = {wa.x, wa.y, wa.z, wa.w, wb.x, wb.y, wb.z, wb.w};
#pragma unroll
            for (int m = 0; m < 8; m++) {
                ull wd; PACK2(wd, wr[m], wr[m]);
                FMA2(acc[m][0], la.x, wd);
                FMA2(acc[m][1], la.y, wd);
                FMA2(acc[m][2], lb.x, wd);
                FMA2(acc[m][3], lb.y, wd);
            }
        }
#pragma unroll
        for (int m = 0; m < 8; m++) {
            float o[8];
#pragma unroll
            for (int jp = 0; jp < 4; jp++) UNPACK2(o[2 * jp], o[2 * jp + 1], acc[m][jp]);
            size_t row = (size_t)((s << 8) + nbase + m0 + m);
            const float* fp = g_f + row * 128 + j0;
            float4 fa = *(const float4*)fp;
            float4 fb = *(const float4*)(fp + 4);
            float* yp = g_fI + row * 128 + j0;
            *(float4*)yp       = make_float4(o[0] * fa.x, o[1] * fa.y, o[2] * fa.z, o[3] * fa.w);
            *(float4*)(yp + 4) = make_float4(o[4] * fb.x, o[5] * fb.y, o[6] * fb.z, o[7] * fb.w);
        }
    }
}

// ================= fused rel MLP + combine, 64-row blocks, 3 blocks/SM =================
__global__ __launch_bounds__(256, 3) void relcomb_kernel(const float* __restrict__ rel_w1,
                                                         const float* __restrict__ rel_b1,
                                                         const float* __restrict__ rel_b2,
                                                         float* __restrict__ out) {
    extern __shared__ float smf[];
    uint32_t* hs   = (uint32_t*)smf;      // 64r x 132k; reused as relG after MMA
    uint32_t* wbuf = hs + 64 * 132;       // 2 x (32k x 136n)
    int*      m_s  = (int*)(wbuf + 2 * 32 * 136);  // 64 gathered object indices (+pad)
    float*    w1s  = (float*)wbuf;        // alias: l1-only scratch
    float*    ris  = w1s + 1280;          // 64 x 12
    int tid = threadIdx.x, lane = tid & 31, warp = tid >> 5;
    int gid = lane >> 2, tig = lane & 3;
    int rbase = (warp & 1) * 32, cbase = (warp >> 1) * 32;
    int R = blockIdx.x * 64;

    for (int i = tid; i < 1280; i += 256) w1s[i] = rel_w1[i];
    for (int i = tid; i < 640; i += 256) {
        int r = i / 10, ii = i - r * 10;
        ris[r * 12 + ii] = g_ri[(size_t)R * 10 + i];
    }
    for (int i = tid; i < 64; i += 256) {
        int grow = R + i;
        int cidx = grow / 17;
        m_s[i] = ((cidx >> 8) << 8) + g_knn[grow];
    }
    __syncthreads();

    // layer 1 (fp32): thread owns channel c, half the rows
    {
        int c = tid & 127, rh = tid >> 7;
        float w1c[10];
#pragma unroll
        for (int i = 0; i < 10; i++) w1c[i] = w1s[i * 128 + c];
        float b1c = rel_b1[c];
#pragma unroll 4
        for (int rr = 0; rr < 32; rr++) {
            int r = rh * 32 + rr;
            const float4* rp = (const float4*)(ris + r * 12);
            float4 v0 = rp[0], v1 = rp[1], v2 = rp[2];
            float a = b1c;
            a += v0.x * w1c[0] + v0.y * w1c[1] + v0.z * w1c[2] + v0.w * w1c[3];
            a += v1.x * w1c[4] + v1.y * w1c[5] + v1.z * w1c[6] + v1.w * w1c[7];
            a += v2.x * w1c[8] + v2.y * w1c[9];
            hs[r * 132 + c] = f2tf32(fmaxf(a, 0.f));
        }
    }
    __syncthreads();   // l1 done; wbuf (aliasing w1s/ris) now free

    // stage chunk 0 of pre-converted w2 (uint4 copy, pad 128->136)
    {
        const uint4* src = (const uint4*)g_w2t;
#pragma unroll
        for (int j = 0; j < 4; j++) {
            int e = tid + j * 256;             // uint4 index in 32x128 chunk
            int kk = e >> 5, n4 = e & 31;
            *(uint4*)(wbuf + kk * 136 + n4 * 4) = src[e];
        }
    }
    __syncthreads();

    float acc[2][4][4];
#pragma unroll
    for (int nt = 0; nt < 4; nt++) {
        int col = cbase + nt * 8 + 2 * tig;
        float v0 = rel_b2[col], v1 = rel_b2[col + 1];
#pragma unroll
        for (int mt = 0; mt < 2; mt++) {
            acc[mt][nt][0] = v0; acc[mt][nt][1] = v1;
            acc[mt][nt][2] = v0; acc[mt][nt][3] = v1;
        }
    }

    for (int ch = 0; ch < 4; ch++) {
        uint4 pre[4];
        if (ch < 3) {
            const uint4* src = (const uint4*)(g_w2t + (ch + 1) * 4096);
#pragma unroll
            for (int j = 0; j < 4; j++) pre[j] = src[tid + j * 256];
        }
        uint32_t* wb = wbuf + (ch & 1) * 4352;
#pragma unroll
        for (int ks = 0; ks < 4; ks++) {
            int k0 = ks * 8, kg = ch * 32 + k0;
            uint32_t a[2][4];
#pragma unroll
            for (int mt = 0; mt < 2; mt++) {
                int rb = rbase + mt * 16;
                a[mt][0] = hs[(rb + gid) * 132 + kg + tig];
                a[mt][1] = hs[(rb + gid + 8) * 132 + kg + tig];
                a[mt][2] = hs[(rb + gid) * 132 + kg + tig + 4];
                a[mt][3] = hs[(rb + gid + 8) * 132 + kg + tig + 4];
            }
#pragma unroll
            for (int nt = 0; nt < 4; nt++) {
                uint32_t bb[2];
                int n = cbase + nt * 8 + gid;
                bb[0] = wb[(k0 + tig) * 136 + n];
                bb[1] = wb[(k0 + tig + 4) * 136 + n];
                MMA_TF32(acc[0][nt], a[0], bb);
                MMA_TF32(acc[1][nt], a[1], bb);
            }
        }
        if (ch < 3) {
            uint32_t* wn = wbuf + ((ch + 1) & 1) * 4352;
#pragma unroll
            for (int j = 0; j < 4; j++) {
                int e = tid + j * 256;
                int kk = e >> 5, n4 = e & 31;
                *(uint4*)(wn + kk * 136 + n4 * 4) = pre[j];
            }
        }
        __syncthreads();
    }

    // store rel frags into smem (reuse hs region)
    float* relG = (float*)hs;
#pragma unroll
    for (int mt = 0; mt < 2; mt++) {
        int r1 = rbase + mt * 16 + gid;
#pragma unroll
        for (int nt = 0; nt < 4; nt++) {
            int col = cbase + nt * 8 + 2 * tig;
            *(float2*)(relG + r1 * 132 + col)       = make_float2(acc[mt][nt][0], acc[mt][nt][1]);
            *(float2*)(relG + (r1 + 8) * 132 + col) = make_float2(acc[mt][nt][2], acc[mt][nt][3]);
        }
    }
    __syncthreads();

    // phase 2: per-(center, col) t-sum with fI gather, atomic add into out
    int c_first = R / 17;
    int n_c = (R + 63) / 17 - c_first + 1;
    for (int it = tid; it < n_c * 128; it += 256) {
        int ci = it >> 7, col = it & 127;
        int c = c_first + ci;
        int rlo = c * 17;      if (rlo < R) rlo = R;
        int rhi = c * 17 + 16; if (rhi > R + 63) rhi = R + 63;
        float ssum = 0.f;
        for (int r = rlo; r <= rhi; r++) {
            int m = m_s[r - R];
            ssum += relG[(r - R) * 132 + col] * g_fI[(size_t)m * 128 + col];
        }
        atomicAdd(&out[(size_t)c * 128 + col], ssum);
    }
}

// ================= score: row sums of out =================
__global__ __launch_bounds__(256) void score_kernel(const float* __restrict__ out,
                                                    float* __restrict__ score) {
    int row = blockIdx.x * 8 + (threadIdx.x >> 5);
    int lane = threadIdx.x & 31;
    float4 v = ((const float4*)(out + (size_t)row * 128))[lane];
    float sum = v.x + v.y + v.z + v.w;
#pragma unroll
    for (int off = 16; off > 0; off >>= 1) sum += __shfl_xor_sync(0xffffffffu, sum, off);
    if (lane == 0) score[row] = sum;
}

// ---------------- launch ----------------
extern "C" void kernel_launch(void* const* d_in, const int* in_sizes, int n_in,
                              void* d_out, int out_size) {
    const float* feat      = (const float*)d_in[0];
    const float* coord     = (const float*)d_in[1];
    const float* lang_feat = (const float*)d_in[2];
    const float* lang_mask = (const float*)d_in[3];
    const float* rel_w1    = (const float*)d_in[4];
    const float* rel_b1    = (const float*)d_in[5];
    const float* rel_w2    = (const float*)d_in[6];
    const float* rel_b2    = (const float*)d_in[7];
    const float* lang_w1   = (const float*)d_in[8];
    const float* lang_b1   = (const float*)d_in[9];
    const float* lang_w2   = (const float*)d_in[10];
    const float* lang_b2   = (const float*)d_in[11];
    const float* feat_w1   = (const float*)d_in[12];
    const float* feat_b1   = (const float*)d_in[13];
    const float* feat_w2   = (const float*)d_in[14];
    const float* feat_b2   = (const float*)d_in[15];

    float* out   = (float*)d_out;
    float* score = (float*)d_out + (out_size - SDIM * NOBJ);

    const int MLP64_SMEM  = (64 * 132 + 32 * 136 + 64 * 36) * 4;                   // 60416
    const int ATTINS_SMEM = (128 * 132 + 128 * 44 + 40 * 132 + 40 * 128 + 40) * 4; // 131872
    const int RELC_SMEM   = (64 * 132 + 2 * 32 * 136 + 80) * 4;                    // 68928

    cudaFuncSetAttribute(mlp64_kernel,   cudaFuncAttributeMaxDynamicSharedMemorySize, MLP64_SMEM);
    cudaFuncSetAttribute(attins_kernel,  cudaFuncAttributeMaxDynamicSharedMemorySize, ATTINS_SMEM);
    cudaFuncSetAttribute(relcomb_kernel, cudaFuncAttributeMaxDynamicSharedMemorySize, RELC_SMEM);

    knn_kernel<<<SDIM + 16, NOBJ>>>(coord, rel_w2);                                     // 1
    mlp64_kernel<<<296, 256, MLP64_SMEM>>>(feat, feat_w1, feat_b1, feat_w2, feat_b2,
                                           lang_feat, lang_w1, lang_b1,
                                           lang_w2, lang_b2);                           // 2
    attins_kernel<<<128, 256, ATTINS_SMEM>>>(lang_mask, out);                           // 3
    relcomb_kernel<<<NROWS / 64, 256, RELC_SMEM>>>(rel_w1, rel_b1, rel_b2, out);        // 4 (profiled)
    score_kernel<<<SDIM * NOBJ / 8, 256>>>(out, score);                                 // 5
}

// round 16
// speedup vs baseline: 1.1577x; 1.1577x over previous
#include <cuda_runtime.h>
#include <cstdint>

#define SDIM 64
#define NOBJ 256
#define LSEQ 40
#define OD   128
#define KNB  17
#define NROWS (SDIM * NOBJ * KNB)   // 278528

typedef unsigned long long ull;

#define FMA2(d, a, b) asm("fma.rn.f32x2 %0, %1, %2, %0;" : "+l"(d) : "l"(a), "l"(b))
#define PACK2(d, lo, hi) asm("mov.b64 %0, {%1, %2};" : "=l"(d) : "f"(lo), "f"(hi))
#define UNPACK2(lo, hi, s) asm("mov.b64 {%0, %1}, %2;" : "=f"(lo), "=f"(hi) : "l"(s))

__device__ __forceinline__ uint32_t f2tf32(float f) {
    uint32_t u;
    asm("cvt.rna.tf32.f32 %0, %1;" : "=r"(u) : "f"(f));
    return u;
}

#define MMA_TF32(d, a, b) \
    asm("mma.sync.aligned.m16n8k8.row.col.f32.tf32.tf32.f32 " \
        "{%0,%1,%2,%3},{%4,%5,%6,%7},{%8,%9},{%0,%1,%2,%3};" \
        : "+f"((d)[0]), "+f"((d)[1]), "+f"((d)[2]), "+f"((d)[3]) \
        : "r"((a)[0]), "r"((a)[1]), "r"((a)[2]), "r"((a)[3]), \
          "r"((b)[0]), "r"((b)[1]))

// ---------------- device scratch ----------------
__device__ __align__(16) float g_f[SDIM * NOBJ * OD];
__device__ __align__(16) float g_lang[SDIM * LSEQ * OD];
__device__ __align__(16) float g_ri[NROWS * 10];
__device__ __align__(16) float g_fI[SDIM * NOBJ * OD];     // f * ins, per object
__device__ __align__(16) uint32_t g_w2p[128 * 128];        // rel_w2 tf32, fragment-paired
__device__ int   g_knn[NROWS];

// ---------------- kNN (blocks 0-63) + rel_w2 fragment-pack (blocks 64-79) ----------------
// g_w2p[ch*4096 + ks*1024 + n*8 + tig*2 + q] = tf32( w2[ch*32 + ks*8 + tig + 4q][n] )
__global__ __launch_bounds__(NOBJ) void knn_kernel(const float* __restrict__ coord,
                                                   const float* __restrict__ rel_w2) {
    int b = blockIdx.x;
    int tid = threadIdx.x;
    if (b >= SDIM) {
        int base = (b - SDIM) * 1024;
#pragma unroll
        for (int j = 0; j < 4; j++) {
            int e = base + tid + j * 256;
            int ch = e >> 12, rem = e & 4095;
            int ks = rem >> 10, rem2 = rem & 1023;
            int n = rem2 >> 3, tt = rem2 & 7;
            int tig = tt >> 1, q = tt & 1;
            int k = ch * 32 + ks * 8 + tig + q * 4;
            g_w2p[e] = f2tf32(rel_w2[k * 128 + n]);
        }
        return;
    }
    __shared__ float cs[NOBJ * 3];
    int s = b;
    int n = tid;
    for (int i = n; i < NOBJ * 3; i += NOBJ) cs[i] = coord[s * NOBJ * 3 + i];
    __syncthreads();
    float cx = cs[n * 3 + 0], cy = cs[n * 3 + 1], cz = cs[n * 3 + 2];
    float best[KNB];
    int   bidx[KNB];
#pragma unroll
    for (int t = 0; t < KNB; t++) { best[t] = 3.4e38f; bidx[t] = 0; }
    for (int j = 0; j < NOBJ; j++) {
        float dx = cs[j * 3 + 0] - cx;
        float dy = cs[j * 3 + 1] - cy;
        float dz = cs[j * 3 + 2] - cz;
        float d2 = dx * dx + dy * dy + dz * dz;
        if (d2 < best[KNB - 1]) {
            int p = KNB - 1;
            while (p > 0 && best[p - 1] > d2) {
                best[p] = best[p - 1]; bidx[p] = bidx[p - 1]; p--;
            }
            best[p] = d2; bidx[p] = j;
        }
    }
#pragma unroll
    for (int t = 0; t < KNB; t++) {
        int row = (s * NOBJ + n) * KNB + t;
        int nb = bidx[t];
        g_knn[row] = nb;
        float cnx = cs[nb * 3 + 0], cny = cs[nb * 3 + 1], cnz = cs[nb * 3 + 2];
        float rx = cnx - cx, ry = cny - cy, rz = cnz - cz;
        float dist = sqrtf(rx * rx + ry * ry + rz * rz);
        float* ri = g_ri + row * 10;
        ri[0] = cnx; ri[1] = cny; ri[2] = cnz;
        ri[3] = cx;  ri[4] = cy;  ri[5] = cz;
        ri[6] = rx;  ri[7] = ry;  ri[8] = rz;
        ri[9] = dist;
    }
}

// ---------------- merged 2-layer MLPs, 64-row blocks ----------------
__global__ __launch_bounds__(256, 2) void mlp64_kernel(const float* __restrict__ feat,
                                                       const float* __restrict__ fw1,
                                                       const float* __restrict__ fb1,
                                                       const float* __restrict__ fw2,
                                                       const float* __restrict__ fb2,
                                                       const float* __restrict__ lang_feat,
                                                       const float* __restrict__ lw1,
                                                       const float* __restrict__ lb1,
                                                       const float* __restrict__ lw2,
                                                       const float* __restrict__ lb2) {
    extern __shared__ float smf[];
    uint32_t* hs = (uint32_t*)smf;      // 64r x 132c (tf32 of h)
    uint32_t* ws = hs + 64 * 132;       // 32k x 136n chunk
    uint32_t* xs = ws + 32 * 136;       // 64r x 36k chunk
    int tid = threadIdx.x, lane = tid & 31, warp = tid >> 5;
    int gid = lane >> 2, tig = lane & 3;
    int rbase = (warp & 1) * 32, cbase = (warp >> 1) * 32;

    const float *X, *W1, *B1, *W2, *B2;
    float* Y;
    int IN, row0;
    if (blockIdx.x < 256) {
        X = feat; W1 = fw1; B1 = fb1; W2 = fw2; B2 = fb2;
        Y = g_f; IN = 128; row0 = blockIdx.x * 64;
    } else {
        X = lang_feat; W1 = lw1; B1 = lb1; W2 = lw2; B2 = lb2;
        Y = g_lang; IN = 256; row0 = (blockIdx.x - 256) * 64;
    }

    float acc[2][4][4];
#pragma unroll
    for (int nt = 0; nt < 4; nt++) {
        int col = cbase + nt * 8 + 2 * tig;
        float v0 = B1[col], v1 = B1[col + 1];
#pragma unroll
        for (int mt = 0; mt < 2; mt++) {
            acc[mt][nt][0] = v0; acc[mt][nt][1] = v1;
            acc[mt][nt][2] = v0; acc[mt][nt][3] = v1;
        }
    }
    // ---- layer 1 ----
    for (int kc = 0; kc < IN; kc += 32) {
        __syncthreads();
        for (int i = tid; i < 32 * 128; i += 256) {
            int kk = i >> 7, n = i & 127;
            ws[kk * 136 + n] = f2tf32(W1[(size_t)(kc + kk) * 128 + n]);
        }
        for (int i = tid; i < 64 * 8; i += 256) {
            int r = i >> 3, k4 = i & 7;
            float4 v = *(const float4*)(X + (size_t)(row0 + r) * IN + kc + k4 * 4);
            xs[r * 36 + k4 * 4 + 0] = f2tf32(v.x);
            xs[r * 36 + k4 * 4 + 1] = f2tf32(v.y);
            xs[r * 36 + k4 * 4 + 2] = f2tf32(v.z);
            xs[r * 36 + k4 * 4 + 3] = f2tf32(v.w);
        }
        __syncthreads();
#pragma unroll
        for (int ks = 0; ks < 4; ks++) {
            int k0 = ks * 8;
            uint32_t a[2][4];
#pragma unroll
            for (int mt = 0; mt < 2; mt++) {
                int rb = rbase + mt * 16;
                a[mt][0] = xs[(rb + gid) * 36 + k0 + tig];
                a[mt][1] = xs[(rb + gid + 8) * 36 + k0 + tig];
                a[mt][2] = xs[(rb + gid) * 36 + k0 + tig + 4];
                a[mt][3] = xs[(rb + gid + 8) * 36 + k0 + tig + 4];
            }
#pragma unroll
            for (int nt = 0; nt < 4; nt++) {
                uint32_t bb[2];
                int n = cbase + nt * 8 + gid;
                bb[0] = ws[(k0 + tig) * 136 + n];
                bb[1] = ws[(k0 + tig + 4) * 136 + n];
                MMA_TF32(acc[0][nt], a[0], bb);
                MMA_TF32(acc[1][nt], a[1], bb);
            }
        }
    }
    // store h = relu(acc) as tf32 into hs[r][c]
#pragma unroll
    for (int mt = 0; mt < 2; mt++) {
        int r1 = rbase + mt * 16 + gid;
#pragma unroll
        for (int nt = 0; nt < 4; nt++) {
            int col = cbase + nt * 8 + 2 * tig;
            hs[r1 * 132 + col]           = f2tf32(fmaxf(acc[mt][nt][0], 0.f));
            hs[r1 * 132 + col + 1]       = f2tf32(fmaxf(acc[mt][nt][1], 0.f));
            hs[(r1 + 8) * 132 + col]     = f2tf32(fmaxf(acc[mt][nt][2], 0.f));
            hs[(r1 + 8) * 132 + col + 1] = f2tf32(fmaxf(acc[mt][nt][3], 0.f));
        }
    }
    // ---- layer 2 ----
#pragma unroll
    for (int nt = 0; nt < 4; nt++) {
        int col = cbase + nt * 8 + 2 * tig;
        float v0 = B2[col], v1 = B2[col + 1];
#pragma unroll
        for (int mt = 0; mt < 2; mt++) {
            acc[mt][nt][0] = v0; acc[mt][nt][1] = v1;
            acc[mt][nt][2] = v0; acc[mt][nt][3] = v1;
        }
    }
    for (int kc = 0; kc < 128; kc += 32) {
        __syncthreads();
        for (int i = tid; i < 32 * 128; i += 256) {
            int kk = i >> 7, n = i & 127;
            ws[kk * 136 + n] = f2tf32(W2[(size_t)(kc + kk) * 128 + n]);
        }
        __syncthreads();
#pragma unroll
        for (int ks = 0; ks < 4; ks++) {
            int k0 = ks * 8, kg = kc + k0;
            uint32_t a[2][4];
#pragma unroll
            for (int mt = 0; mt < 2; mt++) {
                int rb = rbase + mt * 16;
                a[mt][0] = hs[(rb + gid) * 132 + kg + tig];
                a[mt][1] = hs[(rb + gid + 8) * 132 + kg + tig];
                a[mt][2] = hs[(rb + gid) * 132 + kg + tig + 4];
                a[mt][3] = hs[(rb + gid + 8) * 132 + kg + tig + 4];
            }
#pragma unroll
            for (int nt = 0; nt < 4; nt++) {
                uint32_t bb[2];
                int n = cbase + nt * 8 + gid;
                bb[0] = ws[(k0 + tig) * 136 + n];
                bb[1] = ws[(k0 + tig + 4) * 136 + n];
                MMA_TF32(acc[0][nt], a[0], bb);
                MMA_TF32(acc[1][nt], a[1], bb);
            }
        }
    }
#pragma unroll
    for (int mt = 0; mt < 2; mt++) {
        int r1 = row0 + rbase + mt * 16 + gid;
#pragma unroll
        for (int nt = 0; nt < 4; nt++) {
            int col = cbase + nt * 8 + 2 * tig;
            *(float2*)(Y + (size_t)r1 * 128 + col)       = make_float2(acc[mt][nt][0], acc[mt][nt][1]);
            *(float2*)(Y + (size_t)(r1 + 8) * 128 + col) = make_float2(acc[mt][nt][2], acc[mt][nt][3]);
        }
    }
}

// ================= attins: logits + softmax + fI = f*(W@lang) + out init, per half-sentence =================
__global__ __launch_bounds__(256) void attins_kernel(const float* __restrict__ lang_mask,
                                                     float* __restrict__ out) {
    extern __shared__ float sm[];
    float* fT     = sm;                   // 128k x 132n
    float* lT     = fT + 128 * 132;       // 128k x 44l
    float* WT     = lT + 128 * 44;        // 40l x 132m
    float* langS  = WT + 40 * 132;        // 40l x 128j
    float* mask_s = langS + 40 * 128;     // 40
    int s = blockIdx.x >> 1, nh = blockIdx.x & 1;
    int nbase = nh * 128;
    int tid = threadIdx.x;

    for (int i = tid; i < 128 * 32; i += 256) {
        int n = i & 127, k4 = i >> 7;
        const float* fp = g_f + (size_t)((s << 8) + nbase + n) * 128;
        float4 v = *(const float4*)(fp + k4 * 4);
        fT[(k4 * 4 + 0) * 132 + n] = v.x;
        fT[(k4 * 4 + 1) * 132 + n] = v.y;
        fT[(k4 * 4 + 2) * 132 + n] = v.z;
        fT[(k4 * 4 + 3) * 132 + n] = v.w;
        ((float4*)(out + (size_t)((s << 8) + nbase + n) * 128))[k4] = v;
    }
    for (int i = tid; i < 40 * 32; i += 256) {
        int l = i % 40, k4 = i / 40;
        float4 v = *(const float4*)(g_lang + (size_t)(s * 40 + l) * 128 + k4 * 4);
        lT[(k4 * 4 + 0) * 44 + l] = v.x;
        lT[(k4 * 4 + 1) * 44 + l] = v.y;
        lT[(k4 * 4 + 2) * 44 + l] = v.z;
        lT[(k4 * 4 + 3) * 44 + l] = v.w;
        ((float4*)(langS + l * 128))[k4] = v;
    }
    if (tid < 40) mask_s[tid] = lang_mask[s * 40 + tid];
    __syncthreads();

    // logits: WT[l][m] = <f_m, lang_l>
    {
        int tn = tid & 31, tl = tid >> 5;
        int n0 = tn * 4, l0 = tl * 5;
        ull acc[2][5];
#pragma unroll
        for (int np = 0; np < 2; np++)
#pragma unroll
            for (int u = 0; u < 5; u++) acc[np][u] = 0ull;
#pragma unroll 2
        for (int k = 0; k < 128; k++) {
            float4 fa = *(const float4*)(fT + k * 132 + n0);
            ull f01, f23;
            PACK2(f01, fa.x, fa.y); PACK2(f23, fa.z, fa.w);
#pragma unroll
            for (int u = 0; u < 5; u++) {
                float lg = lT[k * 44 + l0 + u];
                ull ld; PACK2(ld, lg, lg);
                FMA2(acc[0][u], f01, ld);
                FMA2(acc[1][u], f23, ld);
            }
        }
#pragma unroll
        for (int np = 0; np < 2; np++)
#pragma unroll
            for (int u = 0; u < 5; u++) {
                float a0, a1; UNPACK2(a0, a1, acc[np][u]);
                WT[(l0 + u) * 132 + n0 + 2 * np]     = a0;
                WT[(l0 + u) * 132 + n0 + 2 * np + 1] = a1;
            }
    }
    __syncthreads();

    // masked softmax + renorm per object m
    if (tid < 128) {
        int m = tid;
        float mx = -1e30f;
        for (int l = 0; l < 40; l++) mx = fmaxf(mx, WT[l * 132 + m]);
        float Z = 0.f, Zm = 0.f;
        for (int l = 0; l < 40; l++) {
            float e = __expf(WT[l * 132 + m] - mx);
            Z += e;
            float ew = e * mask_s[l];
            Zm += ew;
            WT[l * 132 + m] = ew;
        }
        float inv = 1.f / (Zm + 1e-7f * Z);
        for (int l = 0; l < 40; l++) WT[l * 132 + m] *= inv;
    }
    __syncthreads();

    // I = W @ lang ; write g_fI = f * I : 8m x 8j per thread
    {
        int tx = tid & 15, ty = tid >> 4;
        int j0 = tx * 8, m0 = ty * 8;
        ull acc[8][4];
#pragma unroll
        for (int m = 0; m < 8; m++)
#pragma unroll
            for (int jp = 0; jp < 4; jp++) acc[m][jp] = 0ull;
#pragma unroll 2
        for (int l = 0; l < 40; l++) {
            ulonglong2 la = *(const ulonglong2*)(langS + l * 128 + j0);
            ulonglong2 lb = *(const ulonglong2*)(langS + l * 128 + j0 + 4);
            float4 wa = *(const float4*)(WT + l * 132 + m0);
            float4 wb = *(const float4*)(WT + l * 132 + m0 + 4);
            float wr[8] = {wa.x, wa.y, wa.z, wa.w, wb.x, wb.y, wb.z, wb.w};
#pragma unroll
            for (int m = 0; m < 8; m++) {
                ull wd; PACK2(wd, wr[m], wr[m]);
                FMA2(acc[m][0], la.x, wd);
                FMA2(acc[m][1], la.y, wd);
                FMA2(acc[m][2], lb.x, wd);
                FMA2(acc[m][3], lb.y, wd);
            }
        }
#pragma unroll
        for (int m = 0; m < 8; m++) {
            float o[8];
#pragma unroll
            for (int jp = 0; jp < 4; jp++) UNPACK2(o[2 * jp], o[2 * jp + 1], acc[m][jp]);
            size_t row = (size_t)((s << 8) + nbase + m0 + m);
            const float* fp = g_f + row * 128 + j0;
            float4 fa = *(const float4*)fp;
            float4 fb = *(const float4*)(fp + 4);
            float* yp = g_fI + row * 128 + j0;
            *(float4*)yp       = make_float4(o[0] * fa.x, o[1] * fa.y, o[2] * fa.z, o[3] * fa.w);
            *(float4*)(yp + 4) = make_float4(o[4] * fb.x, o[5] * fb.y, o[6] * fb.z, o[7] * fb.w);
        }
    }
}

// ================= fused rel MLP + combine (128-row, paired w2 B-fragments) =================
__global__ __launch_bounds__(256, 2) void relcomb_kernel(const float* __restrict__ rel_w1,
                                                         const float* __restrict__ rel_b1,
                                                         const float* __restrict__ rel_b2,
                                                         float* __restrict__ out) {
    extern __shared__ float smf[];
    uint32_t* hs   = (uint32_t*)smf;      // 128r x 132k; reused as relG after MMA
    uint32_t* wbuf = hs + 128 * 132;      // 2 x 4096 (paired chunks, linear)
    int*      m_s  = (int*)(wbuf + 2 * 4096);  // 128 indices
    float*    w1s  = (float*)wbuf;        // alias: l1-only scratch
    float*    ris  = w1s + 1280;
    int tid = threadIdx.x, lane = tid & 31, warp = tid >> 5;
    int gid = lane >> 2, tig = lane & 3;
    int rbase = (warp & 3) * 32, cbase = (warp >> 2) * 64;
    int R = blockIdx.x * 128;

    for (int i = tid; i < 1280; i += 256) w1s[i] = rel_w1[i];
    for (int i = tid; i < 1280; i += 256) {
        int r = i / 10, ii = i - r * 10;
        ris[r * 12 + ii] = g_ri[(size_t)R * 10 + i];
    }
    for (int i = tid; i < 128; i += 256) {
        int grow = R + i;
        int cidx = grow / 17;
        m_s[i] = ((cidx >> 8) << 8) + g_knn[grow];
    }
    __syncthreads();

    // layer 1 (fp32)
    {
        int c = tid & 127, rh = tid >> 7;
        float w1c[10];
#pragma unroll
        for (int i = 0; i < 10; i++) w1c[i] = w1s[i * 128 + c];
        float b1c = rel_b1[c];
#pragma unroll 4
        for (int rr = 0; rr < 64; rr++) {
            int r = rh * 64 + rr;
            const float4* rp = (const float4*)(ris + r * 12);
            float4 v0 = rp[0], v1 = rp[1], v2 = rp[2];
            float a = b1c;
            a += v0.x * w1c[0] + v0.y * w1c[1] + v0.z * w1c[2] + v0.w * w1c[3];
            a += v1.x * w1c[4] + v1.y * w1c[5] + v1.z * w1c[6] + v1.w * w1c[7];
            a += v2.x * w1c[8] + v2.y * w1c[9];
            hs[r * 132 + c] = f2tf32(fmaxf(a, 0.f));
        }
    }
    __syncthreads();   // l1 done; wbuf free

    // stage chunk 0 of paired w2 (linear uint4 copy)
#pragma unroll
    for (int j = 0; j < 4; j++)
        ((uint4*)wbuf)[tid + j * 256] = ((const uint4*)g_w2p)[tid + j * 256];
    __syncthreads();

    float acc[2][8][4];
#pragma unroll
    for (int nt = 0; nt < 8; nt++) {
        int col = cbase + nt * 8 + 2 * tig;
        float v0 = rel_b2[col], v1 = rel_b2[col + 1];
#pragma unroll
        for (int mt = 0; mt < 2; mt++) {
            acc[mt][nt][0] = v0; acc[mt][nt][1] = v1;
            acc[mt][nt][2] = v0; acc[mt][nt][3] = v1;
        }
    }

    for (int ch = 0; ch < 4; ch++) {
        uint4 pre[4];
        if (ch < 3) {
            const uint4* src = (const uint4*)(g_w2p + (ch + 1) * 4096);
#pragma unroll
            for (int j = 0; j < 4; j++) pre[j] = src[tid + j * 256];
        }
        uint32_t* wb = wbuf + (ch & 1) * 4096;
#pragma unroll
        for (int ks = 0; ks < 4; ks++) {
            int kg = ch * 32 + ks * 8;
            uint32_t a[2][4];
#pragma unroll
            for (int mt = 0; mt < 2; mt++) {
                int rb = rbase + mt * 16;
                a[mt][0] = hs[(rb + gid) * 132 + kg + tig];
                a[mt][1] = hs[(rb + gid + 8) * 132 + kg + tig];
                a[mt][2] = hs[(rb + gid) * 132 + kg + tig + 4];
                a[mt][3] = hs[(rb + gid + 8) * 132 + kg + tig + 4];
            }
            const uint32_t* wrow = wb + ks * 1024 + tig * 2;
#pragma unroll
            for (int nt = 0; nt < 8; nt++) {
                int n = cbase + nt * 8 + gid;
                uint2 bv = *(const uint2*)(wrow + n * 8);
                uint32_t bb[2] = {bv.x, bv.y};
                MMA_TF32(acc[0][nt], a[0], bb);
                MMA_TF32(acc[1][nt], a[1], bb);
            }
        }
        if (ch < 3) {
            uint32_t* wn = wbuf + ((ch + 1) & 1) * 4096;
#pragma unroll
            for (int j = 0; j < 4; j++) ((uint4*)wn)[tid + j * 256] = pre[j];
        }
        __syncthreads();
    }

    // store rel frags into smem (reuse hs region)
    float* relG = (float*)hs;
#pragma unroll
    for (int mt = 0; mt < 2; mt++) {
        int r1 = rbase + mt * 16 + gid;
#pragma unroll
        for (int nt = 0; nt < 8; nt++) {
            int col = cbase + nt * 8 + 2 * tig;
            *(float2*)(relG + r1 * 132 + col)       = make_float2(acc[mt][nt][0], acc[mt][nt][1]);
            *(float2*)(relG + (r1 + 8) * 132 + col) = make_float2(acc[mt][nt][2], acc[mt][nt][3]);
        }
    }
    __syncthreads();

    // phase 2: per-(center, col) t-sum with fI gather, atomic add into out
    int c_first = R / 17;
    int n_c = (R + 127) / 17 - c_first + 1;
    for (int it = tid; it < n_c * 128; it += 256) {
        int ci = it >> 7, col = it & 127;
        int c = c_first + ci;
        int rlo = c * 17;      if (rlo < R) rlo = R;
        int rhi = c * 17 + 16; if (rhi > R + 127) rhi = R + 127;
        float ssum = 0.f;
        for (int r = rlo; r <= rhi; r++) {
            int m = m_s[r - R];
            ssum += relG[(r - R) * 132 + col] * g_fI[(size_t)m * 128 + col];
        }
        atomicAdd(&out[(size_t)c * 128 + col], ssum);
    }
}

// ================= score: row sums of out =================
__global__ __launch_bounds__(256) void score_kernel(const float* __restrict__ out,
                                                    float* __restrict__ score) {
    int row = blockIdx.x * 8 + (threadIdx.x >> 5);
    int lane = threadIdx.x & 31;
    float4 v = ((const float4*)(out + (size_t)row * 128))[lane];
    float sum = v.x + v.y + v.z + v.w;
#pragma unroll
    for (int off = 16; off > 0; off >>= 1) sum += __shfl_xor_sync(0xffffffffu, sum, off);
    if (lane == 0) score[row] = sum;
}

// ---------------- launch ----------------
extern "C" void kernel_launch(void* const* d_in, const int* in_sizes, int n_in,
                              void* d_out, int out_size) {
    const float* feat      = (const float*)d_in[0];
    const float* coord     = (const float*)d_in[1];
    const float* lang_feat = (const float*)d_in[2];
    const float* lang_mask = (const float*)d_in[3];
    const float* rel_w1    = (const float*)d_in[4];
    const float* rel_b1    = (const float*)d_in[5];
    const float* rel_w2    = (const float*)d_in[6];
    const float* rel_b2    = (const float*)d_in[7];
    const float* lang_w1   = (const float*)d_in[8];
    const float* lang_b1   = (const float*)d_in[9];
    const float* lang_w2   = (const float*)d_in[10];
    const float* lang_b2   = (const float*)d_in[11];
    const float* feat_w1   = (const float*)d_in[12];
    const float* feat_b1   = (const float*)d_in[13];
    const float* feat_w2   = (const float*)d_in[14];
    const float* feat_b2   = (const float*)d_in[15];

    float* out   = (float*)d_out;
    float* score = (float*)d_out + (out_size - SDIM * NOBJ);

    const int MLP64_SMEM  = (64 * 132 + 32 * 136 + 64 * 36) * 4;                   // 60416
    const int ATTINS_SMEM = (128 * 132 + 128 * 44 + 40 * 132 + 40 * 128 + 40) * 4; // 131872
    const int RELC_SMEM   = (128 * 132 + 2 * 4096 + 128) * 4;                      // 100864

    cudaFuncSetAttribute(mlp64_kernel,   cudaFuncAttributeMaxDynamicSharedMemorySize, MLP64_SMEM);
    cudaFuncSetAttribute(attins_kernel,  cudaFuncAttributeMaxDynamicSharedMemorySize, ATTINS_SMEM);
    cudaFuncSetAttribute(relcomb_kernel, cudaFuncAttributeMaxDynamicSharedMemorySize, RELC_SMEM);

    knn_kernel<<<SDIM + 16, NOBJ>>>(coord, rel_w2);                                     // 1
    mlp64_kernel<<<296, 256, MLP64_SMEM>>>(feat, feat_w1, feat_b1, feat_w2, feat_b2,
                                           lang_feat, lang_w1, lang_b1,
                                           lang_w2, lang_b2);                           // 2
    attins_kernel<<<128, 256, ATTINS_SMEM>>>(lang_mask, out);                           // 3
    relcomb_kernel<<<NROWS / 128, 256, RELC_SMEM>>>(rel_w1, rel_b1, rel_b2, out);       // 4 (profiled)
    score_kernel<<<SDIM * NOBJ / 8, 256>>>(out, score);                                 // 5
}

// round 17
// speedup vs baseline: 1.2634x; 1.0913x over previous
#include <cuda_runtime.h>
#include <cstdint>

#define SDIM 64
#define NOBJ 256
#define LSEQ 40
#define OD   128
#define KNB  17
#define NROWS (SDIM * NOBJ * KNB)   // 278528

typedef unsigned long long ull;

#define FMA2(d, a, b) asm("fma.rn.f32x2 %0, %1, %2, %0;" : "+l"(d) : "l"(a), "l"(b))
#define PACK2(d, lo, hi) asm("mov.b64 %0, {%1, %2};" : "=l"(d) : "f"(lo), "f"(hi))
#define UNPACK2(lo, hi, s) asm("mov.b64 {%0, %1}, %2;" : "=f"(lo), "=f"(hi) : "l"(s))

__device__ __forceinline__ uint32_t f2tf32(float f) {
    uint32_t u;
    asm("cvt.rna.tf32.f32 %0, %1;" : "=r"(u) : "f"(f));
    return u;
}

#define MMA_TF32(d, a, b) \
    asm("mma.sync.aligned.m16n8k8.row.col.f32.tf32.tf32.f32 " \
        "{%0,%1,%2,%3},{%4,%5,%6,%7},{%8,%9},{%0,%1,%2,%3};" \
        : "+f"((d)[0]), "+f"((d)[1]), "+f"((d)[2]), "+f"((d)[3]) \
        : "r"((a)[0]), "r"((a)[1]), "r"((a)[2]), "r"((a)[3]), \
          "r"((b)[0]), "r"((b)[1]))

// ---------------- device scratch ----------------
__device__ __align__(16) float g_f[SDIM * NOBJ * OD];
__device__ __align__(16) float g_lang[SDIM * LSEQ * OD];
__device__ __align__(16) float g_ri[NROWS * 10];
__device__ __align__(16) float g_fI[SDIM * NOBJ * OD];     // f * ins, per object
__device__ __align__(16) uint32_t g_w2p[128 * 128];        // rel_w2 tf32, fragment-paired
__device__ __align__(16) uint32_t g_w1t[16 * 128];         // rel_w1 tf32, k-padded to 16
__device__ int   g_knn[NROWS];

// ---------------- kNN (0-63) + w2 frag-pack (64-79) + w1 tf32-pad (80) ----------------
__global__ __launch_bounds__(NOBJ) void knn_kernel(const float* __restrict__ coord,
                                                   const float* __restrict__ rel_w2,
                                                   const float* __restrict__ rel_w1) {
    int b = blockIdx.x;
    int tid = threadIdx.x;
    if (b == SDIM + 16) {
        for (int i = tid; i < 16 * 128; i += 256) {
            int k = i >> 7, n = i & 127;
            g_w1t[i] = (k < 10) ? f2tf32(rel_w1[k * 128 + n]) : 0u;
        }
        return;
    }
    if (b >= SDIM) {
        int base = (b - SDIM) * 1024;
#pragma unroll
        for (int j = 0; j < 4; j++) {
            int e = base + tid + j * 256;
            int ch = e >> 12, rem = e & 4095;
            int ks = rem >> 10, rem2 = rem & 1023;
            int n = rem2 >> 3, tt = rem2 & 7;
            int tig = tt >> 1, q = tt & 1;
            int k = ch * 32 + ks * 8 + tig + q * 4;
            g_w2p[e] = f2tf32(rel_w2[k * 128 + n]);
        }
        return;
    }
    __shared__ float cs[NOBJ * 3];
    int s = b;
    int n = tid;
    for (int i = n; i < NOBJ * 3; i += NOBJ) cs[i] = coord[s * NOBJ * 3 + i];
    __syncthreads();
    float cx = cs[n * 3 + 0], cy = cs[n * 3 + 1], cz = cs[n * 3 + 2];
    float best[KNB];
    int   bidx[KNB];
#pragma unroll
    for (int t = 0; t < KNB; t++) { best[t] = 3.4e38f; bidx[t] = 0; }
    for (int j = 0; j < NOBJ; j++) {
        float dx = cs[j * 3 + 0] - cx;
        float dy = cs[j * 3 + 1] - cy;
        float dz = cs[j * 3 + 2] - cz;
        float d2 = dx * dx + dy * dy + dz * dz;
        if (d2 < best[KNB - 1]) {
            int p = KNB - 1;
            while (p > 0 && best[p - 1] > d2) {
                best[p] = best[p - 1]; bidx[p] = bidx[p - 1]; p--;
            }
            best[p] = d2; bidx[p] = j;
        }
    }
#pragma unroll
    for (int t = 0; t < KNB; t++) {
        int row = (s * NOBJ + n) * KNB + t;
        int nb = bidx[t];
        g_knn[row] = nb;
        float cnx = cs[nb * 3 + 0], cny = cs[nb * 3 + 1], cnz = cs[nb * 3 + 2];
        float rx = cnx - cx, ry = cny - cy, rz = cnz - cz;
        float dist = sqrtf(rx * rx + ry * ry + rz * rz);
        float* ri = g_ri + row * 10;
        ri[0] = cnx; ri[1] = cny; ri[2] = cnz;
        ri[3] = cx;  ri[4] = cy;  ri[5] = cz;
        ri[6] = rx;  ri[7] = ry;  ri[8] = rz;
        ri[9] = dist;
    }
}

// ---------------- merged 2-layer MLPs, 64-row blocks ----------------
__global__ __launch_bounds__(256, 2) void mlp64_kernel(const float* __restrict__ feat,
                                                       const float* __restrict__ fw1,
                                                       const float* __restrict__ fb1,
                                                       const float* __restrict__ fw2,
                                                       const float* __restrict__ fb2,
                                                       const float* __restrict__ lang_feat,
                                                       const float* __restrict__ lw1,
                                                       const float* __restrict__ lb1,
                                                       const float* __restrict__ lw2,
                                                       const float* __restrict__ lb2) {
    extern __shared__ float smf[];
    uint32_t* hs = (uint32_t*)smf;      // 64r x 132c
    uint32_t* ws = hs + 64 * 132;       // 32k x 136n chunk
    uint32_t* xs = ws + 32 * 136;       // 64r x 36k chunk
    int tid = threadIdx.x, lane = tid & 31, warp = tid >> 5;
    int gid = lane >> 2, tig = lane & 3;
    int rbase = (warp & 1) * 32, cbase = (warp >> 1) * 32;

    const float *X, *W1, *B1, *W2, *B2;
    float* Y;
    int IN, row0;
    if (blockIdx.x < 256) {
        X = feat; W1 = fw1; B1 = fb1; W2 = fw2; B2 = fb2;
        Y = g_f; IN = 128; row0 = blockIdx.x * 64;
    } else {
        X = lang_feat; W1 = lw1; B1 = lb1; W2 = lw2; B2 = lb2;
        Y = g_lang; IN = 256; row0 = (blockIdx.x - 256) * 64;
    }

    float acc[2][4][4];
#pragma unroll
    for (int nt = 0; nt < 4; nt++) {
        int col = cbase + nt * 8 + 2 * tig;
        float v0 = B1[col], v1 = B1[col + 1];
#pragma unroll
        for (int mt = 0; mt < 2; mt++) {
            acc[mt][nt][0] = v0; acc[mt][nt][1] = v1;
            acc[mt][nt][2] = v0; acc[mt][nt][3] = v1;
        }
    }
    for (int kc = 0; kc < IN; kc += 32) {
        __syncthreads();
        for (int i = tid; i < 32 * 128; i += 256) {
            int kk = i >> 7, n = i & 127;
            ws[kk * 136 + n] = f2tf32(W1[(size_t)(kc + kk) * 128 + n]);
        }
        for (int i = tid; i < 64 * 8; i += 256) {
            int r = i >> 3, k4 = i & 7;
            float4 v = *(const float4*)(X + (size_t)(row0 + r) * IN + kc + k4 * 4);
            xs[r * 36 + k4 * 4 + 0] = f2tf32(v.x);
            xs[r * 36 + k4 * 4 + 1] = f2tf32(v.y);
            xs[r * 36 + k4 * 4 + 2] = f2tf32(v.z);
            xs[r * 36 + k4 * 4 + 3] = f2tf32(v.w);
        }
        __syncthreads();
#pragma unroll
        for (int ks = 0; ks < 4; ks++) {
            int k0 = ks * 8;
            uint32_t a[2][4];
#pragma unroll
            for (int mt = 0; mt < 2; mt++) {
                int rb = rbase + mt * 16;
                a[mt][0] = xs[(rb + gid) * 36 + k0 + tig];
                a[mt][1] = xs[(rb + gid + 8) * 36 + k0 + tig];
                a[mt][2] = xs[(rb + gid) * 36 + k0 + tig + 4];
                a[mt][3] = xs[(rb + gid + 8) * 36 + k0 + tig + 4];
            }
#pragma unroll
            for (int nt = 0; nt < 4; nt++) {
                uint32_t bb[2];
                int n = cbase + nt * 8 + gid;
                bb[0] = ws[(k0 + tig) * 136 + n];
                bb[1] = ws[(k0 + tig + 4) * 136 + n];
                MMA_TF32(acc[0][nt], a[0], bb);
                MMA_TF32(acc[1][nt], a[1], bb);
            }
        }
    }
#pragma unroll
    for (int mt = 0; mt < 2; mt++) {
        int r1 = rbase + mt * 16 + gid;
#pragma unroll
        for (int nt = 0; nt < 4; nt++) {
            int col = cbase + nt * 8 + 2 * tig;
            hs[r1 * 132 + col]           = f2tf32(fmaxf(acc[mt][nt][0], 0.f));
            hs[r1 * 132 + col + 1]       = f2tf32(fmaxf(acc[mt][nt][1], 0.f));
            hs[(r1 + 8) * 132 + col]     = f2tf32(fmaxf(acc[mt][nt][2], 0.f));
            hs[(r1 + 8) * 132 + col + 1] = f2tf32(fmaxf(acc[mt][nt][3], 0.f));
        }
    }
#pragma unroll
    for (int nt = 0; nt < 4; nt++) {
        int col = cbase + nt * 8 + 2 * tig;
        float v0 = B2[col], v1 = B2[col + 1];
#pragma unroll
        for (int mt = 0; mt < 2; mt++) {
            acc[mt][nt][0] = v0; acc[mt][nt][1] = v1;
            acc[mt][nt][2] = v0; acc[mt][nt][3] = v1;
        }
    }
    for (int kc = 0; kc < 128; kc += 32) {
        __syncthreads();
        for (int i = tid; i < 32 * 128; i += 256) {
            int kk = i >> 7, n = i & 127;
            ws[kk * 136 + n] = f2tf32(W2[(size_t)(kc + kk) * 128 + n]);
        }
        __syncthreads();
#pragma unroll
        for (int ks = 0; ks < 4; ks++) {
            int k0 = ks * 8, kg = kc + k0;
            uint32_t a[2][4];
#pragma unroll
            for (int mt = 0; mt < 2; mt++) {
                int rb = rbase + mt * 16;
                a[mt][0] = hs[(rb + gid) * 132 + kg + tig];
                a[mt][1] = hs[(rb + gid + 8) * 132 + kg + tig];
                a[mt][2] = hs[(rb + gid) * 132 + kg + tig + 4];
                a[mt][3] = hs[(rb + gid + 8) * 132 + kg + tig + 4];
            }
#pragma unroll
            for (int nt = 0; nt < 4; nt++) {
                uint32_t bb[2];
                int n = cbase + nt * 8 + gid;
                bb[0] = ws[(k0 + tig) * 136 + n];
                bb[1] = ws[(k0 + tig + 4) * 136 + n];
                MMA_TF32(acc[0][nt], a[0], bb);
                MMA_TF32(acc[1][nt], a[1], bb);
            }
        }
    }
#pragma unroll
    for (int mt = 0; mt < 2; mt++) {
        int r1 = row0 + rbase + mt * 16 + gid;
#pragma unroll
        for (int nt = 0; nt < 4; nt++) {
            int col = cbase + nt * 8 + 2 * tig;
            *(float2*)(Y + (size_t)r1 * 128 + col)       = make_float2(acc[mt][nt][0], acc[mt][nt][1]);
            *(float2*)(Y + (size_t)(r1 + 8) * 128 + col) = make_float2(acc[mt][nt][2], acc[mt][nt][3]);
        }
    }
}

// ================= attins: logits + softmax + fI = f*(W@lang) + out init =================
__global__ __launch_bounds__(256) void attins_kernel(const float* __restrict__ lang_mask,
                                                     float* __restrict__ out) {
    extern __shared__ float sm[];
    float* fT     = sm;                   // 128k x 132n
    float* lT     = fT + 128 * 132;       // 128k x 44l
    float* WT     = lT + 128 * 44;        // 40l x 132m
    float* langS  = WT + 40 * 132;        // 40l x 128j
    float* mask_s = langS + 40 * 128;     // 40
    int s = blockIdx.x >> 1, nh = blockIdx.x & 1;
    int nbase = nh * 128;
    int tid = threadIdx.x;

    for (int i = tid; i < 128 * 32; i += 256) {
        int n = i & 127, k4 = i >> 7;
        const float* fp = g_f + (size_t)((s << 8) + nbase + n) * 128;
        float4 v = *(const float4*)(fp + k4 * 4);
        fT[(k4 * 4 + 0) * 132 + n] = v.x;
        fT[(k4 * 4 + 1) * 132 + n] = v.y;
        fT[(k4 * 4 + 2) * 132 + n] = v.z;
        fT[(k4 * 4 + 3) * 132 + n] = v.w;
        ((float4*)(out + (size_t)((s << 8) + nbase + n) * 128))[k4] = v;
    }
    for (int i = tid; i < 40 * 32; i += 256) {
        int l = i % 40, k4 = i / 40;
        float4 v = *(const float4*)(g_lang + (size_t)(s * 40 + l) * 128 + k4 * 4);
        lT[(k4 * 4 + 0) * 44 + l] = v.x;
        lT[(k4 * 4 + 1) * 44 + l] = v.y;
        lT[(k4 * 4 + 2) * 44 + l] = v.z;
        lT[(k4 * 4 + 3) * 44 + l] = v.w;
        ((float4*)(langS + l * 128))[k4] = v;
    }
    if (tid < 40) mask_s[tid] = lang_mask[s * 40 + tid];
    __syncthreads();

    {
        int tn = tid & 31, tl = tid >> 5;
        int n0 = tn * 4, l0 = tl * 5;
        ull acc[2][5];
#pragma unroll
        for (int np = 0; np < 2; np++)
#pragma unroll
            for (int u = 0; u < 5; u++) acc[np][u] = 0ull;
#pragma unroll 2
        for (int k = 0; k < 128; k++) {
            float4 fa = *(const float4*)(fT + k * 132 + n0);
            ull f01, f23;
            PACK2(f01, fa.x, fa.y); PACK2(f23, fa.z, fa.w);
#pragma unroll
            for (int u = 0; u < 5; u++) {
                float lg = lT[k * 44 + l0 + u];
                ull ld; PACK2(ld, lg, lg);
                FMA2(acc[0][u], f01, ld);
                FMA2(acc[1][u], f23, ld);
            }
        }
#pragma unroll
        for (int np = 0; np < 2; np++)
#pragma unroll
            for (int u = 0; u < 5; u++) {
                float a0, a1; UNPACK2(a0, a1, acc[np][u]);
                WT[(l0 + u) * 132 + n0 + 2 * np]     = a0;
                WT[(l0 + u) * 132 + n0 + 2 * np + 1] = a1;
            }
    }
    __syncthreads();

    if (tid < 128) {
        int m = tid;
        float mx = -1e30f;
        for (int l = 0; l < 40; l++) mx = fmaxf(mx, WT[l * 132 + m]);
        float Z = 0.f, Zm = 0.f;
        for (int l = 0; l < 40; l++) {
            float e = __expf(WT[l * 132 + m] - mx);
            Z += e;
            float ew = e * mask_s[l];
            Zm += ew;
            WT[l * 132 + m] = ew;
        }
        float inv = 1.f / (Zm + 1e-7f * Z);
        for (int l = 0; l < 40; l++) WT[l * 132 + m] *= inv;
    }
    __syncthreads();

    {
        int tx = tid & 15, ty = tid >> 4;
        int j0 = tx * 8, m0 = ty * 8;
        ull acc[8][4];
#pragma unroll
        for (int m = 0; m < 8; m++)
#pragma unroll
            for (int jp = 0; jp < 4; jp++) acc[m][jp] = 0ull;
#pragma unroll 2
        for (int l = 0; l < 40; l++) {
            ulonglong2 la = *(const ulonglong2*)(langS + l * 128 + j0);
            ulonglong2 lb = *(const ulonglong2*)(langS + l * 128 + j0 + 4);
            float4 wa = *(const float4*)(WT + l * 132 + m0);
            float4 wb = *(const float4*)(WT + l * 132 + m0 + 4);
            float wr[8] = {wa.x, wa.y, wa.z, wa.w, wb.x, wb.y, wb.z, wb.w};
#pragma unroll
            for (int m = 0; m < 8; m++) {
                ull wd; PACK2(wd, wr[m], wr[m]);
                FMA2(acc[m][0], la.x, wd);
                FMA2(acc[m][1], la.y, wd);
                FMA2(acc[m][2], lb.x, wd);
                FMA2(acc[m][3], lb.y, wd);
            }
        }
#pragma unroll
        for (int m = 0; m < 8; m++) {
            float o[8];
#pragma unroll
            for (int jp = 0; jp < 4; jp++) UNPACK2(o[2 * jp], o[2 * jp + 1], acc[m][jp]);
            size_t row = (size_t)((s << 8) + nbase + m0 + m);
            const float* fp = g_f + row * 128 + j0;
            float4 fa = *(const float4*)fp;
            float4 fb = *(const float4*)(fp + 4);
            float* yp = g_fI + row * 128 + j0;
            *(float4*)yp       = make_float4(o[0] * fa.x, o[1] * fa.y, o[2] * fa.z, o[3] * fa.w);
            *(float4*)(yp + 4) = make_float4(o[4] * fb.x, o[5] * fb.y, o[6] * fb.z, o[7] * fb.w);
        }
    }
}

// ================= fused rel MLP (both layers MMA) + combine =================
__global__ __launch_bounds__(256, 2) void relcomb_kernel(const float* __restrict__ rel_b1,
                                                         const float* __restrict__ rel_b2,
                                                         float* __restrict__ out) {
    extern __shared__ float smf[];
    uint32_t* hs   = (uint32_t*)smf;           // 128r x 132k; reused as relG
    uint32_t* wbuf = hs + 128 * 132;           // 2 x 4096 (w2 paired chunks)
    int*      m_s  = (int*)(wbuf + 2 * 4096);  // 128
    uint32_t* xs   = wbuf;                     // alias: ri frags 128r x 20k
    uint32_t* w1f  = wbuf + 2560;              // alias: w1 tf32 16k x 136n
    int tid = threadIdx.x, lane = tid & 31, warp = tid >> 5;
    int gid = lane >> 2, tig = lane & 3;
    int rbase = (warp & 3) * 32, cbase = (warp >> 2) * 64;
    int R = blockIdx.x * 128;

    // stage ri as tf32 fragments (k padded to 16, stride 20)
    for (int i = tid; i < 1280; i += 256) {
        int r = i / 10, k = i - r * 10;
        xs[r * 20 + k] = f2tf32(g_ri[(size_t)R * 10 + i]);
    }
    for (int i = tid; i < 768; i += 256) {
        int r = i / 6, k = 10 + (i - r * 6);
        xs[r * 20 + k] = 0u;
    }
    for (int i = tid; i < 2048; i += 256) {
        int k = i >> 7, n = i & 127;
        w1f[k * 136 + n] = g_w1t[i];
    }
    for (int i = tid; i < 128; i += 256) {
        int grow = R + i;
        int cidx = grow / 17;
        m_s[i] = ((cidx >> 8) << 8) + g_knn[grow];
    }
    __syncthreads();

    // ---- layer 1 via MMA: h = ri @ w1 + b1, relu, tf32 -> hs ----
    float acc[2][8][4];
#pragma unroll
    for (int nt = 0; nt < 8; nt++) {
        int col = cbase + nt * 8 + 2 * tig;
        float v0 = rel_b1[col], v1 = rel_b1[col + 1];
#pragma unroll
        for (int mt = 0; mt < 2; mt++) {
            acc[mt][nt][0] = v0; acc[mt][nt][1] = v1;
            acc[mt][nt][2] = v0; acc[mt][nt][3] = v1;
        }
    }
#pragma unroll
    for (int ks = 0; ks < 2; ks++) {
        int k0 = ks * 8;
        uint32_t a[2][4];
#pragma unroll
        for (int mt = 0; mt < 2; mt++) {
            int rb = rbase + mt * 16;
            a[mt][0] = xs[(rb + gid) * 20 + k0 + tig];
            a[mt][1] = xs[(rb + gid + 8) * 20 + k0 + tig];
            a[mt][2] = xs[(rb + gid) * 20 + k0 + tig + 4];
            a[mt][3] = xs[(rb + gid + 8) * 20 + k0 + tig + 4];
        }
#pragma unroll
        for (int nt = 0; nt < 8; nt++) {
            uint32_t bb[2];
            int n = cbase + nt * 8 + gid;
            bb[0] = w1f[(k0 + tig) * 136 + n];
            bb[1] = w1f[(k0 + tig + 4) * 136 + n];
            MMA_TF32(acc[0][nt], a[0], bb);
            MMA_TF32(acc[1][nt], a[1], bb);
        }
    }
#pragma unroll
    for (int mt = 0; mt < 2; mt++) {
        int r1 = rbase + mt * 16 + gid;
#pragma unroll
        for (int nt = 0; nt < 8; nt++) {
            int col = cbase + nt * 8 + 2 * tig;
            hs[r1 * 132 + col]           = f2tf32(fmaxf(acc[mt][nt][0], 0.f));
            hs[r1 * 132 + col + 1]       = f2tf32(fmaxf(acc[mt][nt][1], 0.f));
            hs[(r1 + 8) * 132 + col]     = f2tf32(fmaxf(acc[mt][nt][2], 0.f));
            hs[(r1 + 8) * 132 + col + 1] = f2tf32(fmaxf(acc[mt][nt][3], 0.f));
        }
    }
    __syncthreads();   // hs ready; xs/w1f (wbuf) dead

    // stage chunk 0 of paired w2
#pragma unroll
    for (int j = 0; j < 4; j++)
        ((uint4*)wbuf)[tid + j * 256] = ((const uint4*)g_w2p)[tid + j * 256];
    __syncthreads();

    // ---- layer 2 via MMA ----
#pragma unroll
    for (int nt = 0; nt < 8; nt++) {
        int col = cbase + nt * 8 + 2 * tig;
        float v0 = rel_b2[col], v1 = rel_b2[col + 1];
#pragma unroll
        for (int mt = 0; mt < 2; mt++) {
            acc[mt][nt][0] = v0; acc[mt][nt][1] = v1;
            acc[mt][nt][2] = v0; acc[mt][nt][3] = v1;
        }
    }
    for (int ch = 0; ch < 4; ch++) {
        uint4 pre[4];
        if (ch < 3) {
            const uint4* src = (const uint4*)(g_w2p + (ch + 1) * 4096);
#pragma unroll
            for (int j = 0; j < 4; j++) pre[j] = src[tid + j * 256];
        }
        uint32_t* wb = wbuf + (ch & 1) * 4096;
#pragma unroll
        for (int ks = 0; ks < 4; ks++) {
            int kg = ch * 32 + ks * 8;
            uint32_t a[2][4];
#pragma unroll
            for (int mt = 0; mt < 2; mt++) {
                int rb = rbase + mt * 16;
                a[mt][0] = hs[(rb + gid) * 132 + kg + tig];
                a[mt][1] = hs[(rb + gid + 8) * 132 + kg + tig];
                a[mt][2] = hs[(rb + gid) * 132 + kg + tig + 4];
                a[mt][3] = hs[(rb + gid + 8) * 132 + kg + tig + 4];
            }
            const uint32_t* wrow = wb + ks * 1024 + tig * 2;
#pragma unroll
            for (int nt = 0; nt < 8; nt++) {
                int n = cbase + nt * 8 + gid;
                uint2 bv = *(const uint2*)(wrow + n * 8);
                uint32_t bb[2] = {bv.x, bv.y};
                MMA_TF32(acc[0][nt], a[0], bb);
                MMA_TF32(acc[1][nt], a[1], bb);
            }
        }
        if (ch < 3) {
            uint32_t* wn = wbuf + ((ch + 1) & 1) * 4096;
#pragma unroll
            for (int j = 0; j < 4; j++) ((uint4*)wn)[tid + j * 256] = pre[j];
        }
        __syncthreads();
    }

    // store rel frags into smem (reuse hs region)
    float* relG = (float*)hs;
#pragma unroll
    for (int mt = 0; mt < 2; mt++) {
        int r1 = rbase + mt * 16 + gid;
#pragma unroll
        for (int nt = 0; nt < 8; nt++) {
            int col = cbase + nt * 8 + 2 * tig;
            *(float2*)(relG + r1 * 132 + col)       = make_float2(acc[mt][nt][0], acc[mt][nt][1]);
            *(float2*)(relG + (r1 + 8) * 132 + col) = make_float2(acc[mt][nt][2], acc[mt][nt][3]);
        }
    }
    __syncthreads();

    // phase 2 (float4): per-(center, col4) t-sum with fI gather, atomic add into out
    int c_first = R / 17;
    int n_c = (R + 127) / 17 - c_first + 1;
    for (int it = tid; it < n_c * 32; it += 256) {
        int ci = it >> 5, c4 = it & 31;
        int c = c_first + ci;
        int rlo = c * 17;      if (rlo < R) rlo = R;
        int rhi = c * 17 + 16; if (rhi > R + 127) rhi = R + 127;
        float4 ss = make_float4(0.f, 0.f, 0.f, 0.f);
        for (int r = rlo; r <= rhi; r++) {
            int m = m_s[r - R];
            float4 rg = *(const float4*)(relG + (r - R) * 132 + c4 * 4);
            float4 fi = *(const float4*)(g_fI + (size_t)m * 128 + c4 * 4);
            ss.x += rg.x * fi.x; ss.y += rg.y * fi.y;
            ss.z += rg.z * fi.z; ss.w += rg.w * fi.w;
        }
        float* op = out + (size_t)c * 128 + c4 * 4;
        atomicAdd(op + 0, ss.x);
        atomicAdd(op + 1, ss.y);
        atomicAdd(op + 2, ss.z);
        atomicAdd(op + 3, ss.w);
    }
}

// ================= score: row sums of out =================
__global__ __launch_bounds__(256) void score_kernel(const float* __restrict__ out,
                                                    float* __restrict__ score) {
    int row = blockIdx.x * 8 + (threadIdx.x >> 5);
    int lane = threadIdx.x & 31;
    float4 v = ((const float4*)(out + (size_t)row * 128))[lane];
    float sum = v.x + v.y + v.z + v.w;
#pragma unroll
    for (int off = 16; off > 0; off >>= 1) sum += __shfl_xor_sync(0xffffffffu, sum, off);
    if (lane == 0) score[row] = sum;
}

// ---------------- launch ----------------
extern "C" void kernel_launch(void* const* d_in, const int* in_sizes, int n_in,
                              void* d_out, int out_size) {
    const float* feat      = (const float*)d_in[0];
    const float* coord     = (const float*)d_in[1];
    const float* lang_feat = (const float*)d_in[2];
    const float* lang_mask = (const float*)d_in[3];
    const float* rel_w1    = (const float*)d_in[4];
    const float* rel_b1    = (const float*)d_in[5];
    const float* rel_w2    = (const float*)d_in[6];
    const float* rel_b2    = (const float*)d_in[7];
    const float* lang_w1   = (const float*)d_in[8];
    const float* lang_b1   = (const float*)d_in[9];
    const float* lang_w2   = (const float*)d_in[10];
    const float* lang_b2   = (const float*)d_in[11];
    const float* feat_w1   = (const float*)d_in[12];
    const float* feat_b1   = (const float*)d_in[13];
    const float* feat_w2   = (const float*)d_in[14];
    const float* feat_b2   = (const float*)d_in[15];

    float* out   = (float*)d_out;
    float* score = (float*)d_out + (out_size - SDIM * NOBJ);

    const int MLP64_SMEM  = (64 * 132 + 32 * 136 + 64 * 36) * 4;                   // 60416
    const int ATTINS_SMEM = (128 * 132 + 128 * 44 + 40 * 132 + 40 * 128 + 40) * 4; // 131872
    const int RELC_SMEM   = (128 * 132 + 2 * 4096 + 128) * 4;                      // 100864

    cudaFuncSetAttribute(mlp64_kernel,   cudaFuncAttributeMaxDynamicSharedMemorySize, MLP64_SMEM);
    cudaFuncSetAttribute(attins_kernel,  cudaFuncAttributeMaxDynamicSharedMemorySize, ATTINS_SMEM);
    cudaFuncSetAttribute(relcomb_kernel, cudaFuncAttributeMaxDynamicSharedMemorySize, RELC_SMEM);

    knn_kernel<<<SDIM + 17, NOBJ>>>(coord, rel_w2, rel_w1);                             // 1
    mlp64_kernel<<<296, 256, MLP64_SMEM>>>(feat, feat_w1, feat_b1, feat_w2, feat_b2,
                                           lang_feat, lang_w1, lang_b1,
                                           lang_w2, lang_b2);                           // 2
    attins_kernel<<<128, 256, ATTINS_SMEM>>>(lang_mask, out);                           // 3
    relcomb_kernel<<<NROWS / 128, 256, RELC_SMEM>>>(rel_b1, rel_b2, out);               // 4 (profiled)
    score_kernel<<<SDIM * NOBJ / 8, 256>>>(out, score);                                 // 5
}